// round 9
// baseline (speedup 1.0000x reference)
#include <cuda_runtime.h>
#include <cstdint>

#define S_  512
#define I_  384
#define SI_ (S_*I_)       // 196608
#define II_ (I_*I_)       // 147456
#define H_  8
#define C_  32
#define HC_ 256
#define NE_ (S_*C_)       // 16384

// ---------------- scratch (device globals; no allocations allowed) ----------
// "hl-plane": one u32 per element, (bf16_hi << 16) | bf16_lo(residual)
__device__ uint32_t g_msan[(size_t)SI_*64];    // LN(msa), hl       50 MB
__device__ uint32_t g_v[(size_t)H_*I_*NE_];    // v[h][j][s*32+c]  201 MB
__device__ float    g_gate[(size_t)SI_*HC_];   // sigmoid gate     201 MB
__device__ float    g_wlog[(size_t)H_*II_];    // bias logits       4.7 MB
__device__ uint32_t g_w[(size_t)H_*II_];       // softmax wts, hl   4.7 MB
__device__ uint32_t g_o[(size_t)SI_*HC_];      // gate*weights, hl 201 MB
__device__ uint32_t g_Wv[64*HC_];              // split weights (64,256)
__device__ uint32_t g_Wg[64*HC_];              // (64,256)
__device__ uint32_t g_Wo[HC_*64];              // (256,64)

// ---------------- helpers ---------------------------------------------------
__device__ __forceinline__ float wsum(float v){
    #pragma unroll
    for (int o=16;o;o>>=1) v += __shfl_xor_sync(0xffffffffu, v, o);
    return v;
}
__device__ __forceinline__ float wmax(float v){
    #pragma unroll
    for (int o=16;o;o>>=1) v = fmaxf(v, __shfl_xor_sync(0xffffffffu, v, o));
    return v;
}
__device__ __forceinline__ void cp16(void* s, const void* g){
    uint32_t sa = (uint32_t)__cvta_generic_to_shared(s);
    asm volatile("cp.async.cg.shared.global [%0], [%1], 16;" :: "r"(sa), "l"(g));
}
// pack fp32 -> (hi_bf16<<16)|lo_bf16.  hi = truncation, lo = rn(x - hi).
__device__ __forceinline__ uint32_t pack_hl(float x){
    uint32_t h = __float_as_uint(x) & 0xffff0000u;
    float l = x - __uint_as_float(h);
    uint16_t lb; asm("cvt.rn.bf16.f32 %0, %1;" : "=h"(lb) : "f"(l));
    return h | (uint32_t)lb;
}
__device__ __forceinline__ uint32_t prmt(uint32_t a, uint32_t b, uint32_t c){
    uint32_t d; asm("prmt.b32 %0, %1, %2, %3;" : "=r"(d) : "r"(a), "r"(b), "r"(c));
    return d;
}
__device__ __forceinline__ void mma_bf16(float d[4], const uint32_t a[4], const uint32_t b[2]){
    asm volatile(
        "mma.sync.aligned.m16n8k16.row.col.f32.bf16.bf16.f32 "
        "{%0,%1,%2,%3}, {%4,%5,%6,%7}, {%8,%9}, {%0,%1,%2,%3};"
        : "+f"(d[0]), "+f"(d[1]), "+f"(d[2]), "+f"(d[3])
        : "r"(a[0]), "r"(a[1]), "r"(a[2]), "r"(a[3]), "r"(b[0]), "r"(b[1]));
}

// ---------------- stage 1 (merged prep): weights split + msa LN + pair bias --
// blocks [0,64): weight split; [64, 64+24576): msa LN; rest: pair LN + W_bias.
#define PREP_LN0   64
#define PREP_PB0   (64 + SI_/8)
#define PREP_BLKS  (PREP_PB0 + II_/8)
__global__ void k_prep(const float* __restrict__ msa,
                       const float* __restrict__ lmg, const float* __restrict__ lmb,
                       const float* __restrict__ pair,
                       const float* __restrict__ lpg, const float* __restrict__ lpb,
                       const float* __restrict__ Wv, const float* __restrict__ Wg,
                       const float* __restrict__ Wo, const float* __restrict__ Wb){
    __shared__ float sWb[128*8];
    const int b = blockIdx.x;
    const int wid  = threadIdx.x >> 5;
    const int lane = threadIdx.x & 31;

    if (b < PREP_LN0){                       // ---- weight split (16384 elems each)
        int i = b*256 + threadIdx.x;
        g_Wv[i] = pack_hl(Wv[i]);
        g_Wg[i] = pack_hl(Wg[i]);
        g_Wo[i] = pack_hl(Wo[i]);
        return;
    }
    if (b < PREP_PB0){                       // ---- msa LayerNorm -> hl plane
        int row = (b - PREP_LN0)*8 + wid;
        float2 x = ((const float2*)(msa + (size_t)row*64))[lane];
        float mu = wsum(x.x + x.y) * (1.f/64.f);
        float dx = x.x - mu, dy = x.y - mu;
        float var = wsum(dx*dx + dy*dy) * (1.f/64.f);
        float rs = rsqrtf(var + 1e-5f);
        float2 gv = ((const float2*)lmg)[lane];
        float2 bv = ((const float2*)lmb)[lane];
        uint2 o = make_uint2(pack_hl(dx*rs*gv.x + bv.x), pack_hl(dy*rs*gv.y + bv.y));
        ((uint2*)(g_msan + (size_t)row*64))[lane] = o;
        return;
    }
    // ---- pair LayerNorm + W_bias -> logits
    for (int t=threadIdx.x; t<1024; t+=256) sWb[t] = Wb[t];
    __syncthreads();
    int row = (b - PREP_PB0)*8 + wid;
    float4 x = ((const float4*)(pair + (size_t)row*128))[lane];
    float mu = wsum(x.x + x.y + x.z + x.w) * (1.f/128.f);
    float d0 = x.x-mu, d1 = x.y-mu, d2 = x.z-mu, d3 = x.w-mu;
    float var = wsum(d0*d0 + d1*d1 + d2*d2 + d3*d3) * (1.f/128.f);
    float rs = rsqrtf(var + 1e-5f);
    float4 gv = ((const float4*)lpg)[lane];
    float4 bv = ((const float4*)lpb)[lane];
    float n0 = d0*rs*gv.x + bv.x, n1 = d1*rs*gv.y + bv.y;
    float n2 = d2*rs*gv.z + bv.z, n3 = d3*rs*gv.w + bv.w;
    int k0 = lane*4;
    float res[8];
    #pragma unroll
    for (int h=0; h<8; h++){
        float p = n0*sWb[(k0+0)*8+h] + n1*sWb[(k0+1)*8+h]
                + n2*sWb[(k0+2)*8+h] + n3*sWb[(k0+3)*8+h];
        res[h] = wsum(p);
    }
    if (lane == 0){
        #pragma unroll
        for (int h=0; h<8; h++) g_wlog[(size_t)h*II_ + row] = res[h];
    }
}

// ---------------- stage 2: softmax over j -> hl plane ------------------------
__global__ void k_softmax(){
    const float* p = g_wlog + (size_t)blockIdx.x * I_;   // blockIdx.x = h*384 + i
    uint32_t*   q = g_w    + (size_t)blockIdx.x * I_;
    int t = threadIdx.x;                                 // 128 threads
    int w = t>>5, lane = t&31;
    __shared__ float sm[8];
    float x0 = p[t], x1 = p[t+128], x2 = p[t+256];
    float m = wmax(fmaxf(x0, fmaxf(x1, x2)));
    if (lane==0) sm[w] = m;
    __syncthreads();
    m = fmaxf(fmaxf(sm[0], sm[1]), fmaxf(sm[2], sm[3]));
    float e0 = expf(x0-m), e1 = expf(x1-m), e2 = expf(x2-m);
    float s = wsum(e0 + e1 + e2);
    if (lane==0) sm[4+w] = s;
    __syncthreads();
    float inv = 1.f / (sm[4] + sm[5] + sm[6] + sm[7]);
    q[t] = pack_hl(e0*inv); q[t+128] = pack_hl(e1*inv); q[t+256] = pack_hl(e2*inv);
}

// ---------------- generic pre-split bf16 GEMM + fused epilogues --------------
// EPI 0: A=g_msan [SI,64],  B=Wv|Wg [64,256]+[64,256] -> scatter v(hl) + gate
// EPI 2: A=g_o [SI,256],    B=Wo [256,64]             -> d_out (fp32)
template<int EPI>
__device__ __forceinline__ void store2(int r, int c, float v0, float v1, int z, float* Cout){
    if (EPI == 0){
        int s = r / I_, j = r - s*I_;
        if (c < 256){
            int h = c >> 5, cc = c & 31;
            *(uint2*)&g_v[((size_t)(h*I_ + j) << 14) + s*32 + cc] =
                make_uint2(pack_hl(v0), pack_hl(v1));
        } else {
            *(float2*)&g_gate[(size_t)r*HC_ + (c - 256)] =
                make_float2(1.f/(1.f+expf(-v0)), 1.f/(1.f+expf(-v1)));
        }
    } else if (EPI == 1){
        int s = c >> 5, cc = c & 31;
        size_t oi = ((size_t)s*I_ + r)*HC_ + z*32 + cc;
        float2 gt = *(const float2*)&g_gate[oi];
        *(uint2*)&g_o[oi] = make_uint2(pack_hl(v0*gt.x), pack_hl(v1*gt.y));
    } else {
        *(float2*)&Cout[(size_t)r*64 + c] = make_float2(v0, v1);
    }
}

template<int BM, int BN, int WGM, int WGN, int EPI>
__global__ void __launch_bounds__(WGM*WGN*32, 512/(WGM*WGN*32))
k_gemm(float* __restrict__ Cout){
    static_assert(BM == WGM*64 && BN == WGN*32, "tile mismatch");
    constexpr int BK = 16, NT = WGM*WGN*32;
    constexpr int ASTR = 24;        // conflict-free uint2 A-frag loads
    constexpr int BSTR = BN + 4;    // conflict-free B-frag loads
    constexpr int K   = (EPI==0) ? 64  : 256;
    constexpr int LDA = (EPI==0) ? 64  : 256;
    constexpr int LDB = (EPI==0) ? 256 : 64;
    constexpr int KT  = K / BK;

    __shared__ uint32_t sA[2*BM*ASTR];
    __shared__ uint32_t sB[2*BK*BSTR];

    const int tid = threadIdx.x;
    const int z   = blockIdx.z;
    const int m0  = blockIdx.y * BM;
    const int n0  = blockIdx.x * BN;

    const uint32_t* Ab; const uint32_t* Bb; int nb = n0;
    if (EPI == 0){ Ab = g_msan; if (n0 >= 256){ Bb = g_Wg; nb = n0 - 256; } else Bb = g_Wv; }
    else { Ab = g_o; Bb = g_Wo; }

    const int w = tid>>5, lane = tid&31, gq = lane>>2, tg = lane&3;
    const int wm = (w % WGM) * 64, wn = (w / WGM) * 32;

    float acc[4][4][4];
    #pragma unroll
    for (int i=0;i<4;i++)
    #pragma unroll
    for (int j=0;j<4;j++)
    #pragma unroll
    for (int r=0;r<4;r++) acc[i][j][r] = 0.f;

    auto do_load = [&](int kt){
        const int buf = kt & 1;
        const int k0  = kt * BK;
        uint32_t* As = sA + buf*(BM*ASTR);
        uint32_t* Bs = sB + buf*(BK*BSTR);
        for (int i = tid; i < BM*4; i += NT){            // BM*BK/4 chunks of 16B
            int r = i >> 2, kq = (i & 3) << 2;
            cp16(As + r*ASTR + kq, Ab + (size_t)(m0 + r)*LDA + k0 + kq);
        }
        for (int i = tid; i < BK*(BN/4); i += NT){
            int r = i / (BN/4), cq = (i % (BN/4)) << 2;
            cp16(Bs + r*BSTR + cq, Bb + (size_t)(k0 + r)*LDB + nb + cq);
        }
        asm volatile("cp.async.commit_group;");
    };

    do_load(0);
    for (int kt = 0; kt < KT; kt++){
        if (kt + 1 < KT){ do_load(kt+1); asm volatile("cp.async.wait_group 1;"); }
        else            {                asm volatile("cp.async.wait_group 0;"); }
        __syncthreads();
        const uint32_t* As = sA + (kt&1)*(BM*ASTR);
        const uint32_t* Bs = sB + (kt&1)*(BK*BSTR);

        uint32_t bh[4][2], bl[4][2];
        #pragma unroll
        for (int nt=0; nt<4; nt++){
            const uint32_t* bp = Bs + 2*tg*BSTR + wn + nt*8 + gq;
            uint32_t u0 = bp[0],      u1 = bp[BSTR];
            uint32_t u2 = bp[8*BSTR], u3 = bp[9*BSTR];
            bh[nt][0] = prmt(u0,u1,0x7632u); bl[nt][0] = prmt(u0,u1,0x5410u);
            bh[nt][1] = prmt(u2,u3,0x7632u); bl[nt][1] = prmt(u2,u3,0x5410u);
        }
        #pragma unroll
        for (int mt=0; mt<4; mt++){
            const uint32_t* ap = As + (wm + mt*16 + gq)*ASTR + 2*tg;
            uint2 q0 = *(const uint2*)(ap);
            uint2 q1 = *(const uint2*)(ap + 8*ASTR);
            uint2 q2 = *(const uint2*)(ap + 8);
            uint2 q3 = *(const uint2*)(ap + 8*ASTR + 8);
            uint32_t ah[4], al[4];
            ah[0] = prmt(q0.x,q0.y,0x7632u); al[0] = prmt(q0.x,q0.y,0x5410u);
            ah[1] = prmt(q1.x,q1.y,0x7632u); al[1] = prmt(q1.x,q1.y,0x5410u);
            ah[2] = prmt(q2.x,q2.y,0x7632u); al[2] = prmt(q2.x,q2.y,0x5410u);
            ah[3] = prmt(q3.x,q3.y,0x7632u); al[3] = prmt(q3.x,q3.y,0x5410u);
            #pragma unroll
            for (int nt=0; nt<4; nt++){
                mma_bf16(acc[mt][nt], ah, bl[nt]);   // small terms first
                mma_bf16(acc[mt][nt], al, bh[nt]);
                mma_bf16(acc[mt][nt], ah, bh[nt]);
            }
        }
        __syncthreads();
    }

    #pragma unroll
    for (int mt=0; mt<4; mt++)
    #pragma unroll
    for (int nt=0; nt<4; nt++){
        int r = m0 + wm + mt*16 + gq;
        int c = n0 + wn + nt*8 + 2*tg;
        store2<EPI>(r,   c, acc[mt][nt][0], acc[mt][nt][1], z, Cout);
        store2<EPI>(r+8, c, acc[mt][nt][2], acc[mt][nt][3], z, Cout);
    }
}

// ---------------- stage 5: per-head [384,384]@[384,16384], BM=384 full-M tile -
// grid (256, 1, 8); 384 threads = 12 warps (6 x 2 of 64x32); dynamic smem.
// B (g_v) read exactly once from DRAM; A (g_w) panel is L2-resident per head.
#define G5_ASTR 24
#define G5_BSTR 68
#define G5_SA   (384*G5_ASTR)            // per-buffer u32 count
#define G5_SB   (16*G5_BSTR)
#define G5_SMEM ((2*G5_SA + 2*G5_SB)*4)  // 82432 bytes
__global__ void __launch_bounds__(384, 1) k_gemm5(){
    extern __shared__ uint32_t smem5[];
    uint32_t* sA = smem5;                // 2 * 384*24
    uint32_t* sB = smem5 + 2*G5_SA;      // 2 * 16*68
    constexpr int BK = 16, KT = 384/BK, NT = 384;

    const int tid = threadIdx.x;
    const int z   = blockIdx.z;
    const int n0  = blockIdx.x * 64;

    const uint32_t* Ab = g_w + (size_t)z*II_;           // [384, 384]
    const uint32_t* Bb = g_v + (size_t)z*I_*NE_;        // [384, 16384]

    const int w = tid>>5, lane = tid&31, gq = lane>>2, tg = lane&3;
    const int wm = (w % 6) * 64, wn = (w / 6) * 32;

    float acc[4][4][4];
    #pragma unroll
    for (int i=0;i<4;i++)
    #pragma unroll
    for (int j=0;j<4;j++)
    #pragma unroll
    for (int r=0;r<4;r++) acc[i][j][r] = 0.f;

    auto do_load = [&](int kt){
        const int buf = kt & 1;
        const int k0  = kt * BK;
        uint32_t* As = sA + buf*G5_SA;
        uint32_t* Bs = sB + buf*G5_SB;
        #pragma unroll
        for (int i = tid; i < 384*4; i += NT){           // 4 chunks per thread
            int r = i >> 2, kq = (i & 3) << 2;
            cp16(As + r*G5_ASTR + kq, Ab + (size_t)r*I_ + k0 + kq);
        }
        if (tid < 256){                                  // 16 rows x 16 chunks
            int r = tid >> 4, cq = (tid & 15) << 2;
            cp16(Bs + r*G5_BSTR + cq, Bb + (size_t)(k0 + r)*NE_ + n0 + cq);
        }
        asm volatile("cp.async.commit_group;");
    };

    do_load(0);
    for (int kt = 0; kt < KT; kt++){
        if (kt + 1 < KT){ do_load(kt+1); asm volatile("cp.async.wait_group 1;"); }
        else            {                asm volatile("cp.async.wait_group 0;"); }
        __syncthreads();
        const uint32_t* As = sA + (kt&1)*G5_SA;
        const uint32_t* Bs = sB + (kt&1)*G5_SB;

        uint32_t bh[4][2], bl[4][2];
        #pragma unroll
        for (int nt=0; nt<4; nt++){
            const uint32_t* bp = Bs + 2*tg*G5_BSTR + wn + nt*8 + gq;
            uint32_t u0 = bp[0],         u1 = bp[G5_BSTR];
            uint32_t u2 = bp[8*G5_BSTR], u3 = bp[9*G5_BSTR];
            bh[nt][0] = prmt(u0,u1,0x7632u); bl[nt][0] = prmt(u0,u1,0x5410u);
            bh[nt][1] = prmt(u2,u3,0x7632u); bl[nt][1] = prmt(u2,u3,0x5410u);
        }
        #pragma unroll
        for (int mt=0; mt<4; mt++){
            const uint32_t* ap = As + (wm + mt*16 + gq)*G5_ASTR + 2*tg;
            uint2 q0 = *(const uint2*)(ap);
            uint2 q1 = *(const uint2*)(ap + 8*G5_ASTR);
            uint2 q2 = *(const uint2*)(ap + 8);
            uint2 q3 = *(const uint2*)(ap + 8*G5_ASTR + 8);
            uint32_t ah[4], al[4];
            ah[0] = prmt(q0.x,q0.y,0x7632u); al[0] = prmt(q0.x,q0.y,0x5410u);
            ah[1] = prmt(q1.x,q1.y,0x7632u); al[1] = prmt(q1.x,q1.y,0x5410u);
            ah[2] = prmt(q2.x,q2.y,0x7632u); al[2] = prmt(q2.x,q2.y,0x5410u);
            ah[3] = prmt(q3.x,q3.y,0x7632u); al[3] = prmt(q3.x,q3.y,0x5410u);
            #pragma unroll
            for (int nt=0; nt<4; nt++){
                mma_bf16(acc[mt][nt], ah, bl[nt]);
                mma_bf16(acc[mt][nt], al, bh[nt]);
                mma_bf16(acc[mt][nt], ah, bh[nt]);
            }
        }
        __syncthreads();
    }

    // epilogue: gate * weights -> g_o (hl)
    #pragma unroll
    for (int mt=0; mt<4; mt++)
    #pragma unroll
    for (int nt=0; nt<4; nt++){
        int r = wm + mt*16 + gq;
        int c = n0 + wn + nt*8 + 2*tg;
        store2<1>(r,   c, acc[mt][nt][0], acc[mt][nt][1], z, nullptr);
        store2<1>(r+8, c, acc[mt][nt][2], acc[mt][nt][3], z, nullptr);
    }
}

// ---------------- launch -----------------------------------------------------
extern "C" void kernel_launch(void* const* d_in, const int* /*in_sizes*/, int /*n_in*/,
                              void* d_out, int /*out_size*/){
    const float* msa  = (const float*)d_in[0];
    const float* pair = (const float*)d_in[1];
    const float* lmg  = (const float*)d_in[2];
    const float* lmb  = (const float*)d_in[3];
    const float* lpg  = (const float*)d_in[4];
    const float* lpb  = (const float*)d_in[5];
    const float* Wv   = (const float*)d_in[6];
    const float* Wb   = (const float*)d_in[7];
    const float* Wg   = (const float*)d_in[8];
    const float* Wo   = (const float*)d_in[9];
    float* out = (float*)d_out;

    cudaFuncSetAttribute(k_gemm5, cudaFuncAttributeMaxDynamicSharedMemorySize, G5_SMEM);

    // 1: merged prep (weight split + msa LN + pair LN/bias)
    k_prep<<<PREP_BLKS, 256>>>(msa, lmg, lmb, pair, lpg, lpb, Wv, Wg, Wo, Wb);
    // 2: softmax
    k_softmax<<<H_*I_, 128>>>();
    // 3: stage 4 GEMM: [SI,64] @ [64,512] -> v(hl) + gate
    k_gemm<128,128,2,4,0><<<dim3(512/128, SI_/128, 1), 256>>>(nullptr);
    // 4: stage 5 GEMM (profiled slot): per-head [384,384] @ [384,16384]
    k_gemm5<<<dim3(NE_/64, 1, H_), 384, G5_SMEM>>>();
    // 5: stage 6 GEMM: [SI,256] @ [256,64] -> out
    k_gemm<128, 64,2,2,2><<<dim3(1, SI_/128, 1), 128>>>(out);
}

// round 12
// speedup vs baseline: 1.1909x; 1.1909x over previous
#include <cuda_runtime.h>
#include <cstdint>

#define S_  512
#define I_  384
#define SI_ (S_*I_)       // 196608
#define II_ (I_*I_)       // 147456
#define H_  8
#define C_  32
#define HC_ 256
#define NE_ (S_*C_)       // 16384

// ---------------- scratch (device globals; no allocations allowed) ----------
// "hl-plane": one u32 per element, (bf16_hi << 16) | bf16_lo(residual)
__device__ uint32_t g_msan[(size_t)SI_*64];    // LN(msa), hl       50 MB
__device__ uint32_t g_v[(size_t)H_*I_*NE_];    // v[h][j][s*32+c]  201 MB
__device__ float    g_gate[(size_t)SI_*HC_];   // sigmoid gate     201 MB
__device__ float    g_wlog[(size_t)H_*II_];    // bias logits       4.7 MB
__device__ uint32_t g_w[(size_t)H_*II_];       // softmax wts, hl   4.7 MB
__device__ uint32_t g_o[(size_t)SI_*HC_];      // gate*weights, hl 201 MB
__device__ uint32_t g_Wv[64*HC_];              // split weights (64,256)
__device__ uint32_t g_Wg[64*HC_];              // (64,256)
__device__ uint32_t g_Wo[HC_*64];              // (256,64)

// ---------------- helpers ---------------------------------------------------
__device__ __forceinline__ float wsum(float v){
    #pragma unroll
    for (int o=16;o;o>>=1) v += __shfl_xor_sync(0xffffffffu, v, o);
    return v;
}
__device__ __forceinline__ float wmax(float v){
    #pragma unroll
    for (int o=16;o;o>>=1) v = fmaxf(v, __shfl_xor_sync(0xffffffffu, v, o));
    return v;
}
__device__ __forceinline__ void cp16(void* s, const void* g){
    uint32_t sa = (uint32_t)__cvta_generic_to_shared(s);
    asm volatile("cp.async.cg.shared.global [%0], [%1], 16;" :: "r"(sa), "l"(g));
}
// pack fp32 -> (hi_bf16<<16)|lo_bf16.  hi = truncation, lo = rn(x - hi).
__device__ __forceinline__ uint32_t pack_hl(float x){
    uint32_t h = __float_as_uint(x) & 0xffff0000u;
    float l = x - __uint_as_float(h);
    uint16_t lb; asm("cvt.rn.bf16.f32 %0, %1;" : "=h"(lb) : "f"(l));
    return h | (uint32_t)lb;
}
__device__ __forceinline__ uint32_t prmt(uint32_t a, uint32_t b, uint32_t c){
    uint32_t d; asm("prmt.b32 %0, %1, %2, %3;" : "=r"(d) : "r"(a), "r"(b), "r"(c));
    return d;
}
__device__ __forceinline__ void mma_bf16(float d[4], const uint32_t a[4], const uint32_t b[2]){
    asm volatile(
        "mma.sync.aligned.m16n8k16.row.col.f32.bf16.bf16.f32 "
        "{%0,%1,%2,%3}, {%4,%5,%6,%7}, {%8,%9}, {%0,%1,%2,%3};"
        : "+f"(d[0]), "+f"(d[1]), "+f"(d[2]), "+f"(d[3])
        : "r"(a[0]), "r"(a[1]), "r"(a[2]), "r"(a[3]), "r"(b[0]), "r"(b[1]));
}

// ---------------- stage 1 (merged prep): weights split + msa LN + pair bias --
#define PREP_LN0   64
#define PREP_PB0   (64 + SI_/8)
#define PREP_BLKS  (PREP_PB0 + II_/8)
__global__ void k_prep(const float* __restrict__ msa,
                       const float* __restrict__ lmg, const float* __restrict__ lmb,
                       const float* __restrict__ pair,
                       const float* __restrict__ lpg, const float* __restrict__ lpb,
                       const float* __restrict__ Wv, const float* __restrict__ Wg,
                       const float* __restrict__ Wo, const float* __restrict__ Wb){
    __shared__ float sWb[128*8];
    const int b = blockIdx.x;
    const int wid  = threadIdx.x >> 5;
    const int lane = threadIdx.x & 31;

    if (b < PREP_LN0){                       // ---- weight split (16384 elems each)
        int i = b*256 + threadIdx.x;
        g_Wv[i] = pack_hl(Wv[i]);
        g_Wg[i] = pack_hl(Wg[i]);
        g_Wo[i] = pack_hl(Wo[i]);
        return;
    }
    if (b < PREP_PB0){                       // ---- msa LayerNorm -> hl plane
        int row = (b - PREP_LN0)*8 + wid;
        float2 x = ((const float2*)(msa + (size_t)row*64))[lane];
        float mu = wsum(x.x + x.y) * (1.f/64.f);
        float dx = x.x - mu, dy = x.y - mu;
        float var = wsum(dx*dx + dy*dy) * (1.f/64.f);
        float rs = rsqrtf(var + 1e-5f);
        float2 gv = ((const float2*)lmg)[lane];
        float2 bv = ((const float2*)lmb)[lane];
        uint2 o = make_uint2(pack_hl(dx*rs*gv.x + bv.x), pack_hl(dy*rs*gv.y + bv.y));
        ((uint2*)(g_msan + (size_t)row*64))[lane] = o;
        return;
    }
    // ---- pair LayerNorm + W_bias -> logits
    for (int t=threadIdx.x; t<1024; t+=256) sWb[t] = Wb[t];
    __syncthreads();
    int row = (b - PREP_PB0)*8 + wid;
    float4 x = ((const float4*)(pair + (size_t)row*128))[lane];
    float mu = wsum(x.x + x.y + x.z + x.w) * (1.f/128.f);
    float d0 = x.x-mu, d1 = x.y-mu, d2 = x.z-mu, d3 = x.w-mu;
    float var = wsum(d0*d0 + d1*d1 + d2*d2 + d3*d3) * (1.f/128.f);
    float rs = rsqrtf(var + 1e-5f);
    float4 gv = ((const float4*)lpg)[lane];
    float4 bv = ((const float4*)lpb)[lane];
    float n0 = d0*rs*gv.x + bv.x, n1 = d1*rs*gv.y + bv.y;
    float n2 = d2*rs*gv.z + bv.z, n3 = d3*rs*gv.w + bv.w;
    int k0 = lane*4;
    float res[8];
    #pragma unroll
    for (int h=0; h<8; h++){
        float p = n0*sWb[(k0+0)*8+h] + n1*sWb[(k0+1)*8+h]
                + n2*sWb[(k0+2)*8+h] + n3*sWb[(k0+3)*8+h];
        res[h] = wsum(p);
    }
    if (lane == 0){
        #pragma unroll
        for (int h=0; h<8; h++) g_wlog[(size_t)h*II_ + row] = res[h];
    }
}

// ---------------- stage 2: softmax over j -> hl plane ------------------------
__global__ void k_softmax(){
    const float* p = g_wlog + (size_t)blockIdx.x * I_;   // blockIdx.x = h*384 + i
    uint32_t*   q = g_w    + (size_t)blockIdx.x * I_;
    int t = threadIdx.x;                                 // 128 threads
    int w = t>>5, lane = t&31;
    __shared__ float sm[8];
    float x0 = p[t], x1 = p[t+128], x2 = p[t+256];
    float m = wmax(fmaxf(x0, fmaxf(x1, x2)));
    if (lane==0) sm[w] = m;
    __syncthreads();
    m = fmaxf(fmaxf(sm[0], sm[1]), fmaxf(sm[2], sm[3]));
    float e0 = expf(x0-m), e1 = expf(x1-m), e2 = expf(x2-m);
    float s = wsum(e0 + e1 + e2);
    if (lane==0) sm[4+w] = s;
    __syncthreads();
    float inv = 1.f / (sm[4] + sm[5] + sm[6] + sm[7]);
    q[t] = pack_hl(e0*inv); q[t+128] = pack_hl(e1*inv); q[t+256] = pack_hl(e2*inv);
}

// ---------------- generic pre-split bf16 GEMM, 3-stage pipeline --------------
// EPI 0: A=g_msan [SI,64],  B=Wv|Wg [64,256]+[64,256] -> scatter v(hl) + gate
// EPI 1: A=g_w[h] [384,384], B=g_v[h] [384,16384]     -> g_o = hl(gate*weights)
// EPI 2: A=g_o [SI,256],    B=Wo [256,64]             -> d_out (fp32)
template<int EPI>
__device__ __forceinline__ void store2(int r, int c, float v0, float v1, int z, float* Cout){
    if (EPI == 0){
        int s = r / I_, j = r - s*I_;
        if (c < 256){
            int h = c >> 5, cc = c & 31;
            *(uint2*)&g_v[((size_t)(h*I_ + j) << 14) + s*32 + cc] =
                make_uint2(pack_hl(v0), pack_hl(v1));
        } else {
            *(float2*)&g_gate[(size_t)r*HC_ + (c - 256)] =
                make_float2(1.f/(1.f+expf(-v0)), 1.f/(1.f+expf(-v1)));
        }
    } else if (EPI == 1){
        int s = c >> 5, cc = c & 31;
        size_t oi = ((size_t)s*I_ + r)*HC_ + z*32 + cc;
        float2 gt = *(const float2*)&g_gate[oi];
        *(uint2*)&g_o[oi] = make_uint2(pack_hl(v0*gt.x), pack_hl(v1*gt.y));
    } else {
        *(float2*)&Cout[(size_t)r*64 + c] = make_float2(v0, v1);
    }
}

#define GASTR 24            // conflict-free uint2 A-frag loads
#define GBK   16

template<int BM, int BN, int WGM, int WGN, int EPI>
__global__ void __launch_bounds__(WGM*WGN*32, 512/(WGM*WGN*32))
k_gemm(float* __restrict__ Cout){
    static_assert(BM == WGM*64 && BN == WGN*32, "tile mismatch");
    constexpr int BK = GBK, NT = WGM*WGN*32;
    constexpr int ASTR = GASTR;
    constexpr int BSTR = BN + 4;    // conflict-free B-frag loads
    constexpr int K   = (EPI==0) ? 64  : (EPI==1) ? 384 : 256;
    constexpr int LDA = (EPI==0) ? 64  : (EPI==1) ? 384 : 256;
    constexpr int LDB = (EPI==0) ? 256 : (EPI==1) ? NE_ : 64;
    constexpr int KT  = K / BK;
    constexpr int SASZ = BM*ASTR, SBSZ = BK*BSTR;

    extern __shared__ uint32_t smem[];
    uint32_t* sA = smem;             // 3 * SASZ
    uint32_t* sB = smem + 3*SASZ;    // 3 * SBSZ

    const int tid = threadIdx.x;
    const int z   = blockIdx.z;
    const int m0  = blockIdx.y * BM;
    const int n0  = blockIdx.x * BN;

    const uint32_t* Ab; const uint32_t* Bb; int nb = n0;
    if (EPI == 0){ Ab = g_msan; if (n0 >= 256){ Bb = g_Wg; nb = n0 - 256; } else Bb = g_Wv; }
    else if (EPI == 1){ Ab = g_w + (size_t)z*II_; Bb = g_v + (size_t)z*I_*NE_; }
    else { Ab = g_o; Bb = g_Wo; }

    const int w = tid>>5, lane = tid&31, gq = lane>>2, tg = lane&3;
    const int wm = (w % WGM) * 64, wn = (w / WGM) * 32;

    float acc[4][4][4];
    #pragma unroll
    for (int i=0;i<4;i++)
    #pragma unroll
    for (int j=0;j<4;j++)
    #pragma unroll
    for (int r=0;r<4;r++) acc[i][j][r] = 0.f;

    auto do_load = [&](int kt){
        const int buf = kt % 3;
        const int k0  = kt * BK;
        uint32_t* As = sA + buf*SASZ;
        uint32_t* Bs = sB + buf*SBSZ;
        for (int i = tid; i < BM*4; i += NT){            // BM*BK/4 chunks of 16B
            int r = i >> 2, kq = (i & 3) << 2;
            cp16(As + r*ASTR + kq, Ab + (size_t)(m0 + r)*LDA + k0 + kq);
        }
        for (int i = tid; i < BK*(BN/4); i += NT){
            int r = i / (BN/4), cq = (i % (BN/4)) << 2;
            cp16(Bs + r*BSTR + cq, Bb + (size_t)(k0 + r)*LDB + nb + cq);
        }
        asm volatile("cp.async.commit_group;");
    };

    do_load(0);
    do_load(1);
    for (int kt = 0; kt < KT; kt++){
        // buf kt ready when at most (committed - kt - 1) groups pending
        if (kt + 1 < KT) asm volatile("cp.async.wait_group 1;");
        else             asm volatile("cp.async.wait_group 0;");
        __syncthreads();                     // all warps done reading buf (kt-1)%3
        if (kt + 2 < KT) do_load(kt+2);      // safe: overwrites buf (kt-1)%3

        const uint32_t* As = sA + (kt%3)*SASZ;
        const uint32_t* Bs = sB + (kt%3)*SBSZ;

        uint32_t bh[4][2], bl[4][2];
        #pragma unroll
        for (int nt=0; nt<4; nt++){
            const uint32_t* bp = Bs + 2*tg*BSTR + wn + nt*8 + gq;
            uint32_t u0 = bp[0],      u1 = bp[BSTR];
            uint32_t u2 = bp[8*BSTR], u3 = bp[9*BSTR];
            bh[nt][0] = prmt(u0,u1,0x7632u); bl[nt][0] = prmt(u0,u1,0x5410u);
            bh[nt][1] = prmt(u2,u3,0x7632u); bl[nt][1] = prmt(u2,u3,0x5410u);
        }
        #pragma unroll
        for (int mt=0; mt<4; mt++){
            const uint32_t* ap = As + (wm + mt*16 + gq)*ASTR + 2*tg;
            uint2 q0 = *(const uint2*)(ap);
            uint2 q1 = *(const uint2*)(ap + 8*ASTR);
            uint2 q2 = *(const uint2*)(ap + 8);
            uint2 q3 = *(const uint2*)(ap + 8*ASTR + 8);
            uint32_t ah[4], al[4];
            ah[0] = prmt(q0.x,q0.y,0x7632u); al[0] = prmt(q0.x,q0.y,0x5410u);
            ah[1] = prmt(q1.x,q1.y,0x7632u); al[1] = prmt(q1.x,q1.y,0x5410u);
            ah[2] = prmt(q2.x,q2.y,0x7632u); al[2] = prmt(q2.x,q2.y,0x5410u);
            ah[3] = prmt(q3.x,q3.y,0x7632u); al[3] = prmt(q3.x,q3.y,0x5410u);
            #pragma unroll
            for (int nt=0; nt<4; nt++){
                mma_bf16(acc[mt][nt], ah, bl[nt]);   // small terms first
                mma_bf16(acc[mt][nt], al, bh[nt]);
                mma_bf16(acc[mt][nt], ah, bh[nt]);
            }
        }
    }
    __syncthreads();

    #pragma unroll
    for (int mt=0; mt<4; mt++)
    #pragma unroll
    for (int nt=0; nt<4; nt++){
        int r = m0 + wm + mt*16 + gq;
        int c = n0 + wn + nt*8 + 2*tg;
        store2<EPI>(r,   c, acc[mt][nt][0], acc[mt][nt][1], z, Cout);
        store2<EPI>(r+8, c, acc[mt][nt][2], acc[mt][nt][3], z, Cout);
    }
}

// dynamic smem sizes (3-stage)
constexpr int g_smem_bytes(int BM, int BN){
    return (3*BM*GASTR + 3*GBK*(BN+4))*4;
}

// ---------------- launch -----------------------------------------------------
extern "C" void kernel_launch(void* const* d_in, const int* /*in_sizes*/, int /*n_in*/,
                              void* d_out, int /*out_size*/){
    const float* msa  = (const float*)d_in[0];
    const float* pair = (const float*)d_in[1];
    const float* lmg  = (const float*)d_in[2];
    const float* lmb  = (const float*)d_in[3];
    const float* lpg  = (const float*)d_in[4];
    const float* lpb  = (const float*)d_in[5];
    const float* Wv   = (const float*)d_in[6];
    const float* Wb   = (const float*)d_in[7];
    const float* Wg   = (const float*)d_in[8];
    const float* Wo   = (const float*)d_in[9];
    float* out = (float*)d_out;

    constexpr int SM44 = g_smem_bytes(128,128);   // 62208
    constexpr int SM6  = g_smem_bytes(128, 64);   // 49920
    cudaFuncSetAttribute((const void*)k_gemm<128,128,2,4,0>,
                         cudaFuncAttributeMaxDynamicSharedMemorySize, SM44);
    cudaFuncSetAttribute((const void*)k_gemm<128,128,2,4,1>,
                         cudaFuncAttributeMaxDynamicSharedMemorySize, SM44);
    cudaFuncSetAttribute((const void*)k_gemm<128,64,2,2,2>,
                         cudaFuncAttributeMaxDynamicSharedMemorySize, SM6);

    // 1: merged prep (weight split + msa LN + pair LN/bias)
    k_prep<<<PREP_BLKS, 256>>>(msa, lmg, lmb, pair, lpg, lpb, Wv, Wg, Wo, Wb);
    // 2: softmax
    k_softmax<<<H_*I_, 128>>>();
    // 3: stage 4 GEMM: [SI,64] @ [64,512] -> v(hl) + gate
    k_gemm<128,128,2,4,0><<<dim3(512/128, SI_/128, 1), 256, SM44>>>(nullptr);
    // 4: stage 5 GEMM (profiled slot): per-head [384,384] @ [384,16384]
    k_gemm<128,128,2,4,1><<<dim3(NE_/128, I_/128, H_), 256, SM44>>>(nullptr);
    // 5: stage 6 GEMM: [SI,256] @ [256,64] -> out
    k_gemm<128, 64,2,2,2><<<dim3(1, SI_/128, 1), 128, SM6>>>(out);
}